// round 1
// baseline (speedup 1.0000x reference)
#include <cuda_runtime.h>

#define BB   8
#define NPT  4096
#define DD   64
#define KP   1024
#define NNB  16
#define CC   128
#define CIN  67            // D + 3
#define MT   (BB*KP*NNB)   // 131072 rows
#define EPSBN 1e-5f

// ---------------- scratch (no allocations allowed) ----------------
__device__ float g_h0[(size_t)MT*CIN];   // gathered features [MT,67]
__device__ float g_h1[(size_t)MT*CC];    // layer1 pre-BN     [MT,128]
__device__ float g_h2[(size_t)MT*CC];    // layer2 pre-BN     [MT,128]
__device__ int   g_knn[MT];
__device__ float g_nxyz[BB*KP*3];
__device__ float g_W1T[CIN*CC];
__device__ float g_W2T[CC*CC];
__device__ float g_part[2*1024*CC];      // [sum | sumsq] block partials
__device__ float g_scale[2][CC];
__device__ float g_shift[2][CC];

// ---------------- FPS: one block per batch ----------------
__global__ void fps_kernel(const float* __restrict__ xyz, float* __restrict__ outx) {
    const int b   = blockIdx.x;
    const int tid = threadIdx.x;          // 512 threads
    const float* base = xyz + (size_t)b*NPT*3;

    float px[8], py[8], pz[8], dist[8];
#pragma unroll
    for (int i = 0; i < 8; i++) {
        int p = tid + i*512;
        px[i] = base[p*3+0]; py[i] = base[p*3+1]; pz[i] = base[p*3+2];
        dist[i] = 1e10f;
    }

    __shared__ float s_c[3];
    __shared__ float s_v[16];
    __shared__ int   s_i[16];
    __shared__ int   s_far;

    int far = 0;
    for (int t = 0; t < KP; t++) {
        // owner of `far` broadcasts centroid + writes new_xyz
#pragma unroll
        for (int i = 0; i < 8; i++) {
            int p = tid + i*512;
            if (p == far) {
                s_c[0] = px[i]; s_c[1] = py[i]; s_c[2] = pz[i];
                int o = (b*KP + t)*3;
                g_nxyz[o+0] = px[i]; g_nxyz[o+1] = py[i]; g_nxyz[o+2] = pz[i];
                if (outx) { outx[o+0] = px[i]; outx[o+1] = py[i]; outx[o+2] = pz[i]; }
            }
        }
        __syncthreads();
        float cx = s_c[0], cy = s_c[1], cz = s_c[2];

        float bv = -1.0f; int bi = 1 << 30;
#pragma unroll
        for (int i = 0; i < 8; i++) {
            float dx = px[i]-cx, dy = py[i]-cy, dz = pz[i]-cz;
            float d  = dx*dx + dy*dy + dz*dz;
            dist[i]  = fminf(dist[i], d);
            int p = tid + i*512;
            if (dist[i] > bv || (dist[i] == bv && p < bi)) { bv = dist[i]; bi = p; }
        }
#pragma unroll
        for (int o = 16; o > 0; o >>= 1) {
            float ov = __shfl_down_sync(0xffffffffu, bv, o);
            int   oi = __shfl_down_sync(0xffffffffu, bi, o);
            if (ov > bv || (ov == bv && oi < bi)) { bv = ov; bi = oi; }
        }
        int w = tid >> 5;
        if ((tid & 31) == 0) { s_v[w] = bv; s_i[w] = bi; }
        __syncthreads();
        if (tid < 32) {
            bv = (tid < 16) ? s_v[tid] : -1.0f;
            bi = (tid < 16) ? s_i[tid] : (1 << 30);
#pragma unroll
            for (int o = 8; o > 0; o >>= 1) {
                float ov = __shfl_down_sync(0xffffffffu, bv, o);
                int   oi = __shfl_down_sync(0xffffffffu, bi, o);
                if (ov > bv || (ov == bv && oi < bi)) { bv = ov; bi = oi; }
            }
            if (tid == 0) s_far = bi;
        }
        __syncthreads();
        far = s_far;
    }
}

// ---------------- kNN: one warp per center, 4 warps/block ----------------
__global__ void knn_kernel(const float* __restrict__ xyz) {
    extern __shared__ float sm[];
    float* spx = sm;
    float* spy = sm + NPT;
    float* spz = sm + 2*NPT;
    float* sn  = sm + 3*NPT;

    int cid0 = blockIdx.x * 4;
    int b    = cid0 >> 10;
    const float* base = xyz + (size_t)b*NPT*3;
    for (int j = threadIdx.x; j < NPT; j += 128) {
        float x = base[j*3+0], y = base[j*3+1], z = base[j*3+2];
        spx[j] = x; spy[j] = y; spz[j] = z;
        sn[j]  = x*x + y*y + z*z;
    }
    __syncthreads();

    int w = threadIdx.x >> 5, l = threadIdx.x & 31;
    int cid = cid0 + w;
    float cx = g_nxyz[cid*3+0], cy = g_nxyz[cid*3+1], cz = g_nxyz[cid*3+2];
    float cn = cx*cx + cy*cy + cz*cz;

    float bd[16]; int bi[16];
#pragma unroll
    for (int k = 0; k < 16; k++) { bd[k] = 3.4e38f; bi[k] = 1 << 30; }

    for (int j = l; j < NPT; j += 32) {
        float dot = cx*spx[j] + cy*spy[j] + cz*spz[j];
        float sq  = cn + sn[j] - 2.0f*dot;           // reference's expanded formula
        if (sq < bd[15] || (sq == bd[15] && j < bi[15])) {
            float d = sq; int ii = j;
#pragma unroll
            for (int k = 0; k < 16; k++) {
                bool sw = (d < bd[k]) || (d == bd[k] && ii < bi[k]);
                float td = bd[k]; int ti = bi[k];
                if (sw) { bd[k] = d; bi[k] = ii; d = td; ii = ti; }
            }
        }
    }
    // merge 32 sorted lists -> global top-16
    for (int s = 0; s < 16; s++) {
        float v = bd[0]; int vi = bi[0];
#pragma unroll
        for (int o = 16; o > 0; o >>= 1) {
            float ov = __shfl_xor_sync(0xffffffffu, v, o);
            int   oi = __shfl_xor_sync(0xffffffffu, vi, o);
            if (ov < v || (ov == v && oi < vi)) { v = ov; vi = oi; }
        }
        if (bd[0] == v && bi[0] == vi) {           // unique owner (indices unique)
#pragma unroll
            for (int k = 0; k < 15; k++) { bd[k] = bd[k+1]; bi[k] = bi[k+1]; }
            bd[15] = 3.4e38f; bi[15] = 1 << 30;
        }
        if (l == 0) g_knn[cid*16 + s] = vi;
    }
}

// ---------------- gather + concat into h0 [MT,67] ----------------
__global__ void gather_kernel(const float* __restrict__ xyz,
                              const float* __restrict__ points) {
    int gw = (blockIdx.x * blockDim.x + threadIdx.x) >> 5;   // row = one warp
    int l  = threadIdx.x & 31;
    if (gw >= MT) return;
    int nid = g_knn[gw];
    int bk  = gw >> 4;          // global (b*K + k)
    int b   = gw >> 14;         // K*NN = 16384
    const float* pb = points + ((size_t)b*NPT + nid)*DD;
    const float* xb = xyz + ((size_t)b*NPT + nid)*3;
    const float* cb = g_nxyz + (size_t)bk*3;
    float* out = g_h0 + (size_t)gw*CIN;
    for (int i = l; i < CIN; i += 32)
        out[i] = (i < 3) ? (xb[i] - cb[i]) : pb[i-3];
}

// ---------------- pre-transpose weights ----------------
__global__ void wt_kernel(const float* __restrict__ W1, const float* __restrict__ W2) {
    for (int idx = threadIdx.x; idx < CC*CIN; idx += blockDim.x) {
        int o = idx / CIN, c = idx - o*CIN;
        g_W1T[c*CC + o] = W1[idx];
    }
    for (int idx = threadIdx.x; idx < CC*CC; idx += blockDim.x) {
        int o = idx >> 7, c = idx & 127;
        g_W2T[c*CC + o] = W2[idx];
    }
}

// ---------------- GEMM1: h1 = h0 @ W1^T + b1 ----------------
__global__ void gemm1_kernel(const float* __restrict__ bias) {
    extern __shared__ float sm[];
    float* sA = sm;                 // 128 x 68 (padded)
    float* sB = sm + 128*68;        // 67 x 128 (k-major)
    const int m0 = blockIdx.x * 128;
    const int tid = threadIdx.x;

    for (int idx = tid; idx < 128*CIN; idx += 256) {
        int r = idx / CIN, c = idx - r*CIN;
        sA[r*68 + c] = g_h0[(size_t)m0*CIN + idx];
    }
    for (int idx = tid; idx < CIN*CC; idx += 256) sB[idx] = g_W1T[idx];
    __syncthreads();

    const int ty = tid >> 4, tx = tid & 15;
    float acc[8][8];
#pragma unroll
    for (int i = 0; i < 8; i++)
#pragma unroll
        for (int j = 0; j < 8; j++) acc[i][j] = 0.0f;

#pragma unroll 2
    for (int k = 0; k < CIN; k++) {
        float a[8];
#pragma unroll
        for (int i = 0; i < 8; i++) a[i] = sA[(ty*8 + i)*68 + k];
        float4 q0 = *(const float4*)(sB + k*CC + tx*8);
        float4 q1 = *(const float4*)(sB + k*CC + tx*8 + 4);
        float bb[8] = {q0.x,q0.y,q0.z,q0.w,q1.x,q1.y,q1.z,q1.w};
#pragma unroll
        for (int i = 0; i < 8; i++)
#pragma unroll
            for (int j = 0; j < 8; j++) acc[i][j] = fmaf(a[i], bb[j], acc[i][j]);
    }
    float4 bv0 = *(const float4*)(bias + tx*8);
    float4 bv1 = *(const float4*)(bias + tx*8 + 4);
    float bb[8] = {bv0.x,bv0.y,bv0.z,bv0.w,bv1.x,bv1.y,bv1.z,bv1.w};
#pragma unroll
    for (int i = 0; i < 8; i++) {
        size_t ro = (size_t)(m0 + ty*8 + i)*CC + tx*8;
        float4 v0 = make_float4(acc[i][0]+bb[0], acc[i][1]+bb[1], acc[i][2]+bb[2], acc[i][3]+bb[3]);
        float4 v1 = make_float4(acc[i][4]+bb[4], acc[i][5]+bb[5], acc[i][6]+bb[6], acc[i][7]+bb[7]);
        *(float4*)(g_h1 + ro)     = v0;
        *(float4*)(g_h1 + ro + 4) = v1;
    }
}

// ---------------- GEMM2: h2 = relu(bn(h1)) @ W2^T + b2 ----------------
__global__ void gemm2_kernel(const float* __restrict__ bias) {
    extern __shared__ float sm[];
    float* sA = sm;                 // 128 x 65 (KC=64 chunk, padded)
    float* sB = sm + 128*65;        // 64 x 128
    const int m0 = blockIdx.x * 128;
    const int tid = threadIdx.x;
    const int ty = tid >> 4, tx = tid & 15;

    float acc[8][8];
#pragma unroll
    for (int i = 0; i < 8; i++)
#pragma unroll
        for (int j = 0; j < 8; j++) acc[i][j] = 0.0f;

    for (int kc = 0; kc < CC; kc += 64) {
        __syncthreads();
        for (int idx = tid; idx < 128*64; idx += 256) {
            int r = idx >> 6, c = idx & 63;
            int ch = kc + c;
            float x = g_h1[(size_t)(m0 + r)*CC + ch];
            sA[r*65 + c] = fmaxf(fmaf(x, g_scale[0][ch], g_shift[0][ch]), 0.0f);
        }
        for (int idx = tid; idx < 64*CC; idx += 256) sB[idx] = g_W2T[kc*CC + idx];
        __syncthreads();

#pragma unroll 2
        for (int k = 0; k < 64; k++) {
            float a[8];
#pragma unroll
            for (int i = 0; i < 8; i++) a[i] = sA[(ty*8 + i)*65 + k];
            float4 q0 = *(const float4*)(sB + k*CC + tx*8);
            float4 q1 = *(const float4*)(sB + k*CC + tx*8 + 4);
            float bb[8] = {q0.x,q0.y,q0.z,q0.w,q1.x,q1.y,q1.z,q1.w};
#pragma unroll
            for (int i = 0; i < 8; i++)
#pragma unroll
                for (int j = 0; j < 8; j++) acc[i][j] = fmaf(a[i], bb[j], acc[i][j]);
        }
    }
    float4 bv0 = *(const float4*)(bias + tx*8);
    float4 bv1 = *(const float4*)(bias + tx*8 + 4);
    float bb[8] = {bv0.x,bv0.y,bv0.z,bv0.w,bv1.x,bv1.y,bv1.z,bv1.w};
#pragma unroll
    for (int i = 0; i < 8; i++) {
        size_t ro = (size_t)(m0 + ty*8 + i)*CC + tx*8;
        float4 v0 = make_float4(acc[i][0]+bb[0], acc[i][1]+bb[1], acc[i][2]+bb[2], acc[i][3]+bb[3]);
        float4 v1 = make_float4(acc[i][4]+bb[4], acc[i][5]+bb[5], acc[i][6]+bb[6], acc[i][7]+bb[7]);
        *(float4*)(g_h2 + ro)     = v0;
        *(float4*)(g_h2 + ro + 4) = v1;
    }
}

// ---------------- column sum/sumsq partials (deterministic) ----------------
__global__ void colsum_kernel(int layer) {
    const float* X = layer ? g_h2 : g_h1;
    int blk = blockIdx.x;            // 1024 blocks x 128 rows
    int ch  = threadIdx.x;           // 128 threads
    const float* p = X + (size_t)blk*128*CC + ch;
    float s = 0.0f, sq = 0.0f;
#pragma unroll 4
    for (int r = 0; r < 128; r++) {
        float v = p[(size_t)r*CC];
        s += v; sq = fmaf(v, v, sq);
    }
    g_part[blk*CC + ch]           = s;
    g_part[1024*CC + blk*CC + ch] = sq;
}

__global__ void bnfin_kernel(int layer, const float* __restrict__ g,
                             const float* __restrict__ be) {
    int ch = threadIdx.x;
    float s = 0.0f, sq = 0.0f;
    for (int i = 0; i < 1024; i++) {
        s  += g_part[i*CC + ch];
        sq += g_part[1024*CC + i*CC + ch];
    }
    float inv = 1.0f / (float)MT;
    float mean = s * inv;
    float var  = sq * inv - mean*mean;
    float rs   = rsqrtf(var + EPSBN);
    float sc   = rs * g[ch];
    g_scale[layer][ch] = sc;
    g_shift[layer][ch] = be[ch] - mean*sc;
}

// ---------------- final: relu(bn(h2)) max over NN ----------------
__global__ void final_kernel(float* __restrict__ out, int off) {
    int bk = blockIdx.x;             // 8192 blocks
    int ch = threadIdx.x;            // 128
    const float* p = g_h2 + (size_t)bk*NNB*CC + ch;
    float sc = g_scale[1][ch], sh = g_shift[1][ch];
    float m = -3.4e38f;
#pragma unroll
    for (int s = 0; s < NNB; s++)
        m = fmaxf(m, fmaxf(fmaf(p[(size_t)s*CC], sc, sh), 0.0f));
    out[(size_t)off + (size_t)bk*CC + ch] = m;
}

// ---------------- launch ----------------
extern "C" void kernel_launch(void* const* d_in, const int* in_sizes, int n_in,
                              void* d_out, int out_size) {
    const float* xyz    = (const float*)d_in[0];
    const float* points = (const float*)d_in[1];
    const float* W1     = (const float*)d_in[2];
    const float* b1     = (const float*)d_in[3];
    const float* g1     = (const float*)d_in[4];
    const float* be1    = (const float*)d_in[5];
    const float* W2     = (const float*)d_in[6];
    const float* b2     = (const float*)d_in[7];
    const float* g2     = (const float*)d_in[8];
    const float* be2    = (const float*)d_in[9];
    float* out = (float*)d_out;

    // does d_out include new_xyz (tuple concat) or only new_points?
    const int has_xyz = (out_size >= BB*KP*3 + BB*KP*CC) ? 1 : 0;
    float* outx = has_xyz ? out : nullptr;
    const int poff = has_xyz ? BB*KP*3 : 0;

    const int knn_smem  = 4*NPT*(int)sizeof(float);            // 64 KB
    const int g1_smem   = (128*68 + CIN*CC)*(int)sizeof(float); // ~69 KB
    const int g2_smem   = (128*65 + 64*CC)*(int)sizeof(float);  // ~66 KB
    cudaFuncSetAttribute(knn_kernel,  cudaFuncAttributeMaxDynamicSharedMemorySize, knn_smem);
    cudaFuncSetAttribute(gemm1_kernel,cudaFuncAttributeMaxDynamicSharedMemorySize, g1_smem);
    cudaFuncSetAttribute(gemm2_kernel,cudaFuncAttributeMaxDynamicSharedMemorySize, g2_smem);

    fps_kernel<<<BB, 512>>>(xyz, outx);
    wt_kernel<<<1, 256>>>(W1, W2);
    knn_kernel<<<(BB*KP)/4, 128, knn_smem>>>(xyz);
    gather_kernel<<<MT/8, 256>>>(xyz, points);
    gemm1_kernel<<<MT/128, 256, g1_smem>>>(b1);
    colsum_kernel<<<1024, 128>>>(0);
    bnfin_kernel<<<1, 128>>>(0, g1, be1);
    gemm2_kernel<<<MT/128, 256, g2_smem>>>(b2);
    colsum_kernel<<<1024, 128>>>(1);
    bnfin_kernel<<<1, 128>>>(1, g2, be2);
    final_kernel<<<BB*KP, 128>>>(out, poff);
}

// round 2
// speedup vs baseline: 1.3759x; 1.3759x over previous
#include <cuda_runtime.h>

#define BB   8
#define NPT  4096
#define DD   64
#define KP   1024
#define NNB  16
#define CC   128
#define CIN  67            // D + 3
#define MT   (BB*KP*NNB)   // 131072 rows
#define EPSBN 1e-5f

// ---------------- scratch ----------------
__device__ float g_h1[(size_t)MT*CC];
__device__ float g_h2[(size_t)MT*CC];
__device__ int   g_knn[MT];
__device__ float g_nxyz[BB*KP*3];
__device__ float g_W1T[CIN*CC];
__device__ float g_W2T[CC*CC];
__device__ float g_part[2*1024*CC];
__device__ float g_scale[2][CC];
__device__ float g_shift[2][CC];

// ---------------- helpers ----------------
__device__ __forceinline__ unsigned redux_max_u32(unsigned v) {
    unsigned r; asm("redux.sync.max.u32 %0,%1,0xffffffff;" : "=r"(r) : "r"(v)); return r;
}
__device__ __forceinline__ unsigned redux_min_u32(unsigned v) {
    unsigned r; asm("redux.sync.min.u32 %0,%1,0xffffffff;" : "=r"(r) : "r"(v)); return r;
}
__device__ __forceinline__ void fma2(unsigned long long& d, unsigned long long a, unsigned long long b) {
    asm("fma.rn.f32x2 %0,%1,%2,%0;" : "+l"(d) : "l"(a), "l"(b));
}
__device__ __forceinline__ float2 u2f(unsigned long long v) {
    float2 f; asm("mov.b64 {%0,%1},%2;" : "=f"(f.x), "=f"(f.y) : "l"(v)); return f;
}

// ---------------- FPS: one block/batch, 1024 threads, redux argmax ----------------
__global__ void fps_kernel(const float* __restrict__ xyz, float* __restrict__ outx) {
    extern __shared__ float fsm[];
    float* sx = fsm;
    float* sy = fsm + NPT;
    float* sz = fsm + 2*NPT;
    unsigned* swv = (unsigned*)(fsm + 3*NPT);
    unsigned* swi = swv + 32;
    int* sfar = (int*)(swi + 32);

    const int b   = blockIdx.x;
    const int tid = threadIdx.x;            // 1024 threads
    const int lane = tid & 31, warp = tid >> 5;
    const float* base = xyz + (size_t)b*NPT*3;

    float px[4], py[4], pz[4], dist[4];
#pragma unroll
    for (int i = 0; i < 4; i++) {
        int p = tid + i*1024;
        float x = base[p*3+0], y = base[p*3+1], z = base[p*3+2];
        px[i] = x; py[i] = y; pz[i] = z;
        sx[p] = x; sy[p] = y; sz[p] = z;
        dist[i] = 1e10f;
    }
    __syncthreads();

    int far = 0;
    for (int t = 0; t < KP; t++) {
        float cx = sx[far], cy = sy[far], cz = sz[far];
        if (tid == 0) {
            int o = (b*KP + t)*3;
            g_nxyz[o+0] = cx; g_nxyz[o+1] = cy; g_nxyz[o+2] = cz;
            if (outx) { outx[o+0] = cx; outx[o+1] = cy; outx[o+2] = cz; }
        }
        float bv; unsigned bi;
#pragma unroll
        for (int i = 0; i < 4; i++) {
            float dx = px[i]-cx, dy = py[i]-cy, dz = pz[i]-cz;
            float d  = dx*dx + dy*dy + dz*dz;
            dist[i]  = fminf(dist[i], d);
            if (i == 0) { bv = dist[0]; bi = (unsigned)tid; }
            else if (dist[i] > bv) { bv = dist[i]; bi = (unsigned)(tid + i*1024); }
        }
        unsigned vb = __float_as_uint(bv);
        unsigned wm = redux_max_u32(vb);
        unsigned ci = (vb == wm) ? bi : 0xFFFFFFFFu;
        unsigned wi = redux_min_u32(ci);
        if (lane == 0) { swv[warp] = wm; swi[warp] = wi; }
        __syncthreads();
        if (warp == 0) {
            unsigned v  = swv[lane];
            unsigned ii = swi[lane];
            unsigned m  = redux_max_u32(v);
            unsigned c2 = (v == m) ? ii : 0xFFFFFFFFu;
            unsigned f  = redux_min_u32(c2);
            if (lane == 0) *sfar = (int)f;
        }
        __syncthreads();
        far = *sfar;
    }
}

// ---------------- kNN: one warp per center (unchanged, correct) ----------------
__global__ void knn_kernel(const float* __restrict__ xyz) {
    extern __shared__ float sm[];
    float* spx = sm;
    float* spy = sm + NPT;
    float* spz = sm + 2*NPT;
    float* sn  = sm + 3*NPT;

    int cid0 = blockIdx.x * 4;
    int b    = cid0 >> 10;
    const float* base = xyz + (size_t)b*NPT*3;
    for (int j = threadIdx.x; j < NPT; j += 128) {
        float x = base[j*3+0], y = base[j*3+1], z = base[j*3+2];
        spx[j] = x; spy[j] = y; spz[j] = z;
        sn[j]  = x*x + y*y + z*z;
    }
    __syncthreads();

    int w = threadIdx.x >> 5, l = threadIdx.x & 31;
    int cid = cid0 + w;
    float cx = g_nxyz[cid*3+0], cy = g_nxyz[cid*3+1], cz = g_nxyz[cid*3+2];
    float cn = cx*cx + cy*cy + cz*cz;

    float bd[16]; int bi[16];
#pragma unroll
    for (int k = 0; k < 16; k++) { bd[k] = 3.4e38f; bi[k] = 1 << 30; }

    for (int j = l; j < NPT; j += 32) {
        float dot = cx*spx[j] + cy*spy[j] + cz*spz[j];
        float sq  = cn + sn[j] - 2.0f*dot;
        if (sq < bd[15] || (sq == bd[15] && j < bi[15])) {
            float d = sq; int ii = j;
#pragma unroll
            for (int k = 0; k < 16; k++) {
                bool sw = (d < bd[k]) || (d == bd[k] && ii < bi[k]);
                float td = bd[k]; int ti = bi[k];
                if (sw) { bd[k] = d; bi[k] = ii; d = td; ii = ti; }
            }
        }
    }
    for (int s = 0; s < 16; s++) {
        float v = bd[0]; int vi = bi[0];
#pragma unroll
        for (int o = 16; o > 0; o >>= 1) {
            float ov = __shfl_xor_sync(0xffffffffu, v, o);
            int   oi = __shfl_xor_sync(0xffffffffu, vi, o);
            if (ov < v || (ov == v && oi < vi)) { v = ov; vi = oi; }
        }
        if (bd[0] == v && bi[0] == vi) {
#pragma unroll
            for (int k = 0; k < 15; k++) { bd[k] = bd[k+1]; bi[k] = bi[k+1]; }
            bd[15] = 3.4e38f; bi[15] = 1 << 30;
        }
        if (l == 0) g_knn[cid*16 + s] = vi;
    }
}

// ---------------- pre-transpose weights (k-major) ----------------
__global__ void wt_kernel(const float* __restrict__ W1, const float* __restrict__ W2) {
    for (int idx = threadIdx.x; idx < CC*CIN; idx += blockDim.x) {
        int o = idx / CIN, c = idx - o*CIN;
        g_W1T[c*CC + o] = W1[idx];
    }
    for (int idx = threadIdx.x; idx < CC*CC; idx += blockDim.x) {
        int o = idx >> 7, c = idx & 127;
        g_W2T[c*CC + o] = W2[idx];
    }
}

// ---------------- GEMM1 (fused gather): h1 = gather(h0) @ W1^T + b1 ----------------
// sA2: k-major, value-duplicated A tile: [CIN][256] (stride 264), sB: [CIN][128]
#define SA2_STRIDE 264
__global__ void gemm1_kernel(const float* __restrict__ xyz,
                             const float* __restrict__ points,
                             const float* __restrict__ bias) {
    extern __shared__ float sm[];
    float* sA2 = sm;                          // CIN * 264 floats
    float* sB  = sm + CIN*SA2_STRIDE;         // CIN * 128 floats
    __shared__ int   s_nid[128];
    __shared__ float s_ctr[128*3];

    const int m0 = blockIdx.x * 128;
    const int tid = threadIdx.x;              // 256 threads

    if (tid < 128) {
        int gw = m0 + tid;
        s_nid[tid] = g_knn[gw];
        int bk = gw >> 4;
        s_ctr[tid*3+0] = g_nxyz[bk*3+0];
        s_ctr[tid*3+1] = g_nxyz[bk*3+1];
        s_ctr[tid*3+2] = g_nxyz[bk*3+2];
    }
    __syncthreads();

    // gather + transpose + duplicate into sA2
    for (int idx = tid; idx < 128*CIN; idx += 256) {
        int r = idx / CIN, c = idx - r*CIN;
        int nid = s_nid[r];
        int b = (m0 + r) >> 14;               // K*NN = 16384 rows/batch
        float v;
        if (c < 3) v = xyz[((size_t)b*NPT + nid)*3 + c] - s_ctr[r*3 + c];
        else       v = points[((size_t)b*NPT + nid)*DD + (c-3)];
        *(float2*)(sA2 + c*SA2_STRIDE + 2*r) = make_float2(v, v);
    }
    for (int idx = tid; idx < CIN*CC; idx += 256) sB[idx] = g_W1T[idx];
    __syncthreads();

    const int ty = tid >> 4, tx = tid & 15;
    unsigned long long acc[8][4];
#pragma unroll
    for (int i = 0; i < 8; i++)
#pragma unroll
        for (int j = 0; j < 4; j++) acc[i][j] = 0ull;

#pragma unroll 2
    for (int k = 0; k < CIN; k++) {
        const float* pa = sA2 + k*SA2_STRIDE + ty*16;
        ulonglong2 a01 = *(const ulonglong2*)(pa + 0);
        ulonglong2 a23 = *(const ulonglong2*)(pa + 4);
        ulonglong2 a45 = *(const ulonglong2*)(pa + 8);
        ulonglong2 a67 = *(const ulonglong2*)(pa + 12);
        ulonglong2 b01 = *(const ulonglong2*)(sB + k*CC + tx*8);
        ulonglong2 b23 = *(const ulonglong2*)(sB + k*CC + tx*8 + 4);
        unsigned long long av[8] = {a01.x,a01.y,a23.x,a23.y,a45.x,a45.y,a67.x,a67.y};
        unsigned long long bv[4] = {b01.x,b01.y,b23.x,b23.y};
#pragma unroll
        for (int i = 0; i < 8; i++)
#pragma unroll
            for (int j = 0; j < 4; j++) fma2(acc[i][j], av[i], bv[j]);
    }
    float4 q0 = *(const float4*)(bias + tx*8);
    float4 q1 = *(const float4*)(bias + tx*8 + 4);
    float bb[8] = {q0.x,q0.y,q0.z,q0.w,q1.x,q1.y,q1.z,q1.w};
#pragma unroll
    for (int i = 0; i < 8; i++) {
        size_t ro = (size_t)(m0 + ty*8 + i)*CC + tx*8;
        float2 p0 = u2f(acc[i][0]), p1 = u2f(acc[i][1]);
        float2 p2 = u2f(acc[i][2]), p3 = u2f(acc[i][3]);
        *(float4*)(g_h1 + ro)     = make_float4(p0.x+bb[0], p0.y+bb[1], p1.x+bb[2], p1.y+bb[3]);
        *(float4*)(g_h1 + ro + 4) = make_float4(p2.x+bb[4], p2.y+bb[5], p3.x+bb[6], p3.y+bb[7]);
    }
}

// ---------------- GEMM2: h2 = relu(bn(h1)) @ W2^T + b2 ----------------
__global__ void gemm2_kernel(const float* __restrict__ bias) {
    extern __shared__ float sm[];
    float* sA2 = sm;                          // 64 * 264 floats
    float* sB  = sm + 64*SA2_STRIDE;          // 64 * 128 floats
    const int m0 = blockIdx.x * 128;
    const int tid = threadIdx.x;
    const int ty = tid >> 4, tx = tid & 15;

    unsigned long long acc[8][4];
#pragma unroll
    for (int i = 0; i < 8; i++)
#pragma unroll
        for (int j = 0; j < 4; j++) acc[i][j] = 0ull;

    for (int kc = 0; kc < CC; kc += 64) {
        __syncthreads();
        for (int idx = tid; idx < 128*64; idx += 256) {
            int r = idx >> 6, c = idx & 63;
            int ch = kc + c;
            float x = g_h1[(size_t)(m0 + r)*CC + ch];
            float v = fmaxf(fmaf(x, g_scale[0][ch], g_shift[0][ch]), 0.0f);
            *(float2*)(sA2 + c*SA2_STRIDE + 2*r) = make_float2(v, v);
        }
        for (int idx = tid; idx < 64*CC; idx += 256) sB[idx] = g_W2T[kc*CC + idx];
        __syncthreads();

#pragma unroll 2
        for (int k = 0; k < 64; k++) {
            const float* pa = sA2 + k*SA2_STRIDE + ty*16;
            ulonglong2 a01 = *(const ulonglong2*)(pa + 0);
            ulonglong2 a23 = *(const ulonglong2*)(pa + 4);
            ulonglong2 a45 = *(const ulonglong2*)(pa + 8);
            ulonglong2 a67 = *(const ulonglong2*)(pa + 12);
            ulonglong2 b01 = *(const ulonglong2*)(sB + k*CC + tx*8);
            ulonglong2 b23 = *(const ulonglong2*)(sB + k*CC + tx*8 + 4);
            unsigned long long av[8] = {a01.x,a01.y,a23.x,a23.y,a45.x,a45.y,a67.x,a67.y};
            unsigned long long bv[4] = {b01.x,b01.y,b23.x,b23.y};
#pragma unroll
            for (int i = 0; i < 8; i++)
#pragma unroll
                for (int j = 0; j < 4; j++) fma2(acc[i][j], av[i], bv[j]);
        }
    }
    float4 q0 = *(const float4*)(bias + tx*8);
    float4 q1 = *(const float4*)(bias + tx*8 + 4);
    float bb[8] = {q0.x,q0.y,q0.z,q0.w,q1.x,q1.y,q1.z,q1.w};
#pragma unroll
    for (int i = 0; i < 8; i++) {
        size_t ro = (size_t)(m0 + ty*8 + i)*CC + tx*8;
        float2 p0 = u2f(acc[i][0]), p1 = u2f(acc[i][1]);
        float2 p2 = u2f(acc[i][2]), p3 = u2f(acc[i][3]);
        *(float4*)(g_h2 + ro)     = make_float4(p0.x+bb[0], p0.y+bb[1], p1.x+bb[2], p1.y+bb[3]);
        *(float4*)(g_h2 + ro + 4) = make_float4(p2.x+bb[4], p2.y+bb[5], p3.x+bb[6], p3.y+bb[7]);
    }
}

// ---------------- column sum/sumsq partials (deterministic) ----------------
__global__ void colsum_kernel(int layer) {
    const float* X = layer ? g_h2 : g_h1;
    int blk = blockIdx.x;
    int ch  = threadIdx.x;
    const float* p = X + (size_t)blk*128*CC + ch;
    float s = 0.0f, sq = 0.0f;
#pragma unroll 4
    for (int r = 0; r < 128; r++) {
        float v = p[(size_t)r*CC];
        s += v; sq = fmaf(v, v, sq);
    }
    g_part[blk*CC + ch]           = s;
    g_part[1024*CC + blk*CC + ch] = sq;
}

__global__ void bnfin_kernel(int layer, const float* __restrict__ g,
                             const float* __restrict__ be) {
    int ch = threadIdx.x;
    float s = 0.0f, sq = 0.0f;
    for (int i = 0; i < 1024; i++) {
        s  += g_part[i*CC + ch];
        sq += g_part[1024*CC + i*CC + ch];
    }
    float inv = 1.0f / (float)MT;
    float mean = s * inv;
    float var  = sq * inv - mean*mean;
    float rs   = rsqrtf(var + EPSBN);
    float sc   = rs * g[ch];
    g_scale[layer][ch] = sc;
    g_shift[layer][ch] = be[ch] - mean*sc;
}

// ---------------- final: relu(bn(h2)) max over NN ----------------
__global__ void final_kernel(float* __restrict__ out, int off) {
    int bk = blockIdx.x;
    int ch = threadIdx.x;
    const float* p = g_h2 + (size_t)bk*NNB*CC + ch;
    float sc = g_scale[1][ch], sh = g_shift[1][ch];
    float m = -3.4e38f;
#pragma unroll
    for (int s = 0; s < NNB; s++)
        m = fmaxf(m, fmaxf(fmaf(p[(size_t)s*CC], sc, sh), 0.0f));
    out[(size_t)off + (size_t)bk*CC + ch] = m;
}

// ---------------- launch ----------------
extern "C" void kernel_launch(void* const* d_in, const int* in_sizes, int n_in,
                              void* d_out, int out_size) {
    const float* xyz    = (const float*)d_in[0];
    const float* points = (const float*)d_in[1];
    const float* W1     = (const float*)d_in[2];
    const float* b1     = (const float*)d_in[3];
    const float* g1     = (const float*)d_in[4];
    const float* be1    = (const float*)d_in[5];
    const float* W2     = (const float*)d_in[6];
    const float* b2     = (const float*)d_in[7];
    const float* g2     = (const float*)d_in[8];
    const float* be2    = (const float*)d_in[9];
    float* out = (float*)d_out;

    const int has_xyz = (out_size >= BB*KP*3 + BB*KP*CC) ? 1 : 0;
    float* outx = has_xyz ? out : nullptr;
    const int poff = has_xyz ? BB*KP*3 : 0;

    const int fps_smem  = (3*NPT + 64 + 4)*(int)sizeof(float) + 16;
    const int knn_smem  = 4*NPT*(int)sizeof(float);
    const int g1_smem   = (CIN*SA2_STRIDE + CIN*CC)*(int)sizeof(float);
    const int g2_smem   = (64*SA2_STRIDE + 64*CC)*(int)sizeof(float);
    cudaFuncSetAttribute(fps_kernel,  cudaFuncAttributeMaxDynamicSharedMemorySize, fps_smem);
    cudaFuncSetAttribute(knn_kernel,  cudaFuncAttributeMaxDynamicSharedMemorySize, knn_smem);
    cudaFuncSetAttribute(gemm1_kernel,cudaFuncAttributeMaxDynamicSharedMemorySize, g1_smem);
    cudaFuncSetAttribute(gemm2_kernel,cudaFuncAttributeMaxDynamicSharedMemorySize, g2_smem);

    fps_kernel<<<BB, 1024, fps_smem>>>(xyz, outx);
    wt_kernel<<<1, 256>>>(W1, W2);
    knn_kernel<<<(BB*KP)/4, 128, knn_smem>>>(xyz);
    gemm1_kernel<<<MT/128, 256, g1_smem>>>(xyz, points, b1);
    colsum_kernel<<<1024, 128>>>(0);
    bnfin_kernel<<<1, 128>>>(0, g1, be1);
    gemm2_kernel<<<MT/128, 256, g2_smem>>>(b2);
    colsum_kernel<<<1024, 128>>>(1);
    bnfin_kernel<<<1, 128>>>(1, g2, be2);
    final_kernel<<<BB*KP, 128>>>(out, poff);
}